// round 4
// baseline (speedup 1.0000x reference)
#include <cuda_runtime.h>

// ---------------------------------------------------------------------------
// MultilayerGRU: B=32, S=4096, H=256, O=256, L=2
// Persistent-kernel GRU (weights resident in SMEM, grid barrier between
// phases) + deferred output-projection GEMM.
// ---------------------------------------------------------------------------

#define BATCH 32
#define HID   256
#define SEQ   4096
#define OUTD  256
#define NCTA  64
#define NCOL  4      // gate columns owned per CTA (256/64)
#define NTHR  256

#define OUT_HID_OFF (BATCH * SEQ * OUTD)   // 33554432: start of hidden_state in d_out

// ---- persistent-kernel SMEM layout (in floats) ----
#define SW_OFF     0
#define SW_SZ      (12 * NCOL * HID)            // 12288 (12 weight slices)
#define SX_OFF     (SW_OFF + SW_SZ)             // x_t stage [32][256]
#define SH0_OFF    (SX_OFF + BATCH * HID)
#define SH1_OFF    (SH0_OFF + BATCH * HID)
#define SHR_OFF    (SH1_OFF + BATCH * HID)
#define SP_OFF     (SHR_OFF + BATCH * HID)      // parts [4][32][4] = 512
#define SZG_OFF    (SP_OFF + 512)               // z-gate store [32][4] = 128
#define SBIAS_OFF  (SZG_OFF + 128)              // 6 gates x 4 cols (pad to 32)
#define SMEM_FLOATS (SBIAS_OFF + 32)
#define SMEM_BYTES  (SMEM_FLOATS * 4)           // 182912 bytes

// ---- y-projection kernel SMEM ----
#define YW_STR 260                               // padded Why row stride (floats)
#define YSMEM_FLOATS (64 * YW_STR + 32 * HID)    // 16640 + 8192
#define YSMEM_BYTES  (YSMEM_FLOATS * 4)          // 99328 bytes

// ---- persistent state (static device memory: allowed; no runtime allocs) ----
__device__ float    g_h0[BATCH * HID];
__device__ float    g_h1[BATCH * HID];
__device__ float    g_hr[BATCH * HID];
__device__ float    g_h1all[BATCH * SEQ * HID];  // 134 MB: h1 history for y-pass
__device__ unsigned g_bar;

__global__ void bar_init_kernel() { g_bar = 0u; }

// ---------------------------------------------------------------------------
// helpers
// ---------------------------------------------------------------------------

__device__ __forceinline__ void fma2(unsigned long long& acc,
                                     unsigned long long a, unsigned long long b) {
    asm("fma.rn.f32x2 %0, %1, %2, %0;" : "+l"(acc) : "l"(a), "l"(b));
}

__device__ __forceinline__ float red2(unsigned long long a) {
    float lo = __uint_as_float((unsigned)(a & 0xffffffffull));
    float hi = __uint_as_float((unsigned)(a >> 32));
    return lo + hi;
}

__device__ __forceinline__ float sigm(float x) {
    return 1.0f / (1.0f + expf(-x));
}

// grid barrier: monotonic counter, release-arrive / acquire-spin
__device__ __forceinline__ void gbarrier(unsigned target) {
    __threadfence();
    __syncthreads();
    if (threadIdx.x == 0) {
        asm volatile("red.release.gpu.global.add.u32 [%0], %1;"
                     :: "l"(&g_bar), "r"(1u) : "memory");
        unsigned v = 0;
        do {
            asm volatile("ld.acquire.gpu.global.u32 %0, [%1];"
                         : "=r"(v) : "l"(&g_bar) : "memory");
        } while (v < target);
    }
    __syncthreads();
}

// One GEMM job: 2 warps compute, for 32 batches x 4 owned cols,
// partial dots over k in [kb, kb+32*iters). Results -> partOut[b] (float4 of 4 cols).
// half = warp&1, q = lane>>3, ks = lane&7. Thread covers batches b0..b0+3,
// k-chunks k = kb + 32*i + 4*ks  (LDS.128, quarter-warp-uniform batch -> no conflicts).
__device__ __forceinline__ void job_gemm(const float* __restrict__ v,
                                         const float* __restrict__ w,
                                         int kb, int iters,
                                         float4* __restrict__ partOut,
                                         int half, int q, int ks) {
    unsigned long long acc[4][4];
#pragma unroll
    for (int a = 0; a < 4; ++a)
#pragma unroll
        for (int c = 0; c < 4; ++c) acc[a][c] = 0ull;

    const int b0 = half * 16 + q * 4;
    for (int i = 0; i < iters; ++i) {
        const int k = kb + 32 * i + 4 * ks;
        ulonglong2 vv[4];
#pragma unroll
        for (int jj = 0; jj < 4; ++jj)
            vv[jj] = *reinterpret_cast<const ulonglong2*>(v + (b0 + jj) * HID + k);
#pragma unroll
        for (int c = 0; c < 4; ++c) {
            ulonglong2 wv = *reinterpret_cast<const ulonglong2*>(w + c * HID + k);
#pragma unroll
            for (int jj = 0; jj < 4; ++jj) {
                fma2(acc[jj][c], wv.x, vv[jj].x);
                fma2(acc[jj][c], wv.y, vv[jj].y);
            }
        }
    }
    // reduce over the 8 k-slices (lane bits 0..2), lane ks==0 writes
#pragma unroll
    for (int jj = 0; jj < 4; ++jj) {
        float4 r;
        float* rp = &r.x;
#pragma unroll
        for (int c = 0; c < 4; ++c) {
            float f = red2(acc[jj][c]);
            f += __shfl_xor_sync(0xffffffffu, f, 1);
            f += __shfl_xor_sync(0xffffffffu, f, 2);
            f += __shfl_xor_sync(0xffffffffu, f, 4);
            rp[c] = f;
        }
        if (ks == 0) partOut[b0 + jj] = r;
    }
}

// cooperative copy of a [32][256] float block global -> smem (2048 float4)
__device__ __forceinline__ void stage_vec(float* dst, const float* src, int tid) {
    const float4* s = reinterpret_cast<const float4*>(src);
    float4* d = reinterpret_cast<float4*>(dst);
#pragma unroll
    for (int u = 0; u < 8; ++u) d[tid + 256 * u] = s[tid + 256 * u];
}

// ---------------------------------------------------------------------------
// persistent GRU kernel: grid = 64 CTAs, 256 threads
// weight slice order in SMEM: 0:Wxz0 1:Whz0 2:Wxr0 3:Whr0 4:Wxg0 5:Whg0
//                             6:Wxz1 7:Whz1 8:Wxr1 9:Whr1 10:Wxg1 11:Whg1
// ---------------------------------------------------------------------------
__global__ void __launch_bounds__(NTHR, 1)
gru_persistent(const float* __restrict__ input, const float* __restrict__ hstate,
               const float* __restrict__ Wxz, const float* __restrict__ Whz,
               const float* __restrict__ bz,
               const float* __restrict__ Wxr, const float* __restrict__ Whr,
               const float* __restrict__ br,
               const float* __restrict__ Wxg, const float* __restrict__ Whg,
               const float* __restrict__ bg,
               float* __restrict__ out) {
    extern __shared__ float sm[];
    float* sW    = sm + SW_OFF;
    float* sX    = sm + SX_OFF;
    float* sH0   = sm + SH0_OFF;
    float* sH1   = sm + SH1_OFF;
    float* sHR   = sm + SHR_OFF;
    float* sPart = sm + SP_OFF;
    float* sZ    = sm + SZG_OFF;
    float* sBias = sm + SBIAS_OFF;

    const int tid  = threadIdx.x;
    const int cta  = blockIdx.x;
    const int wid  = tid >> 5;
    const int lane = tid & 31;
    const int half = wid & 1;
    const int job  = wid >> 1;
    const int q    = lane >> 3;
    const int ks   = lane & 7;

    // ---- load resident weight slices (own 4 columns of each matrix) ----
    {
        const float* wsrc[12] = {
            Wxz, Whz, Wxr, Whr, Wxg, Whg,
            Wxz + HID * HID, Whz + HID * HID, Wxr + HID * HID,
            Whr + HID * HID, Wxg + HID * HID, Whg + HID * HID
        };
#pragma unroll
        for (int m = 0; m < 12; ++m) {
            const float4* s = reinterpret_cast<const float4*>(wsrc[m] + cta * NCOL * HID);
            float4* d = reinterpret_cast<float4*>(sW + m * NCOL * HID);
            for (int u = tid; u < NCOL * HID / 4; u += NTHR) d[u] = s[u];
        }
    }
    // biases: 0:z0 1:r0 2:g0 3:z1 4:r1 5:g1
    if (tid < 24) {
        int g = tid >> 2, c = tid & 3;
        const float* bsrc = (g % 3 == 0) ? bz : ((g % 3 == 1) ? br : bg);
        sBias[g * 4 + c] = bsrc[(g / 3) * HID + cta * NCOL + c];
    }
    // init global hidden state (own columns)
    if (tid < 128) {
        int b = tid >> 2, c = tid & 3, gc = cta * NCOL + c;
        g_h0[b * HID + gc] = hstate[(b * 2 + 0) * HID + gc];
        g_h1[b * HID + gc] = hstate[(b * 2 + 1) * HID + gc];
    }

    unsigned ph = 0;
    gbarrier(++ph * NCTA);

    for (int t = 0; t < SEQ; ++t) {
        // ---- stage x_t (strided rows) and h0 ----
        {
            const int b8 = tid >> 3, c8 = tid & 7;
            const float4* src = reinterpret_cast<const float4*>(input) +
                                (size_t)(b8 * SEQ + t) * (HID / 4);
            float4* dx = reinterpret_cast<float4*>(sX) + b8 * (HID / 4);
#pragma unroll
            for (int u = 0; u < 8; ++u) dx[c8 + 8 * u] = src[c8 + 8 * u];
        }
        stage_vec(sH0, g_h0, tid);
        __syncthreads();

        // ---- P1: z0, r0 (jobs: x@Wxz0, h0@Whz0, x@Wxr0, h0@Whr0) ----
        {
            const float* v = (job & 1) ? sH0 : sX;
            const float* w = sW + job * (NCOL * HID);
            job_gemm(v, w, 0, 8, reinterpret_cast<float4*>(sPart) + job * 32, half, q, ks);
        }
        __syncthreads();
        if (tid < 128) {
            int b = tid >> 2, c = tid & 3, gc = cta * NCOL + c;
            float z = sigm(sPart[tid] + sPart[128 + tid] + sBias[c]);
            float r = sigm(sPart[256 + tid] + sPart[384 + tid] + sBias[4 + c]);
            sZ[tid] = z;
            g_hr[b * HID + gc] = sH0[b * HID + gc] * r;
        }
        gbarrier(++ph * NCTA);

        // ---- P2: g0, h0' (jobs: x@Wxg0 k-halves, hr@Whg0 k-halves) ----
        stage_vec(sHR, g_hr, tid);
        __syncthreads();
        {
            const float* v = (job < 2) ? sX : sHR;
            const float* w = sW + ((job < 2) ? 4 : 5) * (NCOL * HID);
            job_gemm(v, w, (job & 1) * 128, 4,
                     reinterpret_cast<float4*>(sPart) + job * 32, half, q, ks);
        }
        __syncthreads();
        if (tid < 128) {
            int b = tid >> 2, c = tid & 3, gc = cta * NCOL + c;
            float g = tanhf(sPart[tid] + sPart[128 + tid] + sPart[256 + tid] +
                            sPart[384 + tid] + sBias[8 + c]);
            float z = sZ[tid];
            g_h0[b * HID + gc] = z * sH0[b * HID + gc] + (1.0f - z) * g;
        }
        gbarrier(++ph * NCTA);

        // ---- P3: z1, r1 (jobs: h0'@Wxz1, h1@Whz1, h0'@Wxr1, h1@Whr1) ----
        stage_vec(sH0, g_h0, tid);   // new h0'
        stage_vec(sH1, g_h1, tid);   // previous h1
        __syncthreads();
        {
            const float* v = (job & 1) ? sH1 : sH0;
            const float* w = sW + (6 + job) * (NCOL * HID);
            job_gemm(v, w, 0, 8, reinterpret_cast<float4*>(sPart) + job * 32, half, q, ks);
        }
        __syncthreads();
        if (tid < 128) {
            int b = tid >> 2, c = tid & 3, gc = cta * NCOL + c;
            float z = sigm(sPart[tid] + sPart[128 + tid] + sBias[12 + c]);
            float r = sigm(sPart[256 + tid] + sPart[384 + tid] + sBias[16 + c]);
            sZ[tid] = z;
            g_hr[b * HID + gc] = sH1[b * HID + gc] * r;
        }
        gbarrier(++ph * NCTA);

        // ---- P4: g1, h1' (jobs: h0'@Wxg1 k-halves, hr@Whg1 k-halves) ----
        stage_vec(sHR, g_hr, tid);
        __syncthreads();
        {
            const float* v = (job < 2) ? sH0 : sHR;
            const float* w = sW + ((job < 2) ? 10 : 11) * (NCOL * HID);
            job_gemm(v, w, (job & 1) * 128, 4,
                     reinterpret_cast<float4*>(sPart) + job * 32, half, q, ks);
        }
        __syncthreads();
        if (tid < 128) {
            int b = tid >> 2, c = tid & 3, gc = cta * NCOL + c;
            float g = tanhf(sPart[tid] + sPart[128 + tid] + sPart[256 + tid] +
                            sPart[384 + tid] + sBias[20 + c]);
            float z = sZ[tid];
            float hn = z * sH1[b * HID + gc] + (1.0f - z) * g;
            g_h1[b * HID + gc] = hn;
            g_h1all[((size_t)b * SEQ + t) * HID + gc] = hn;  // for deferred y-pass
        }
        gbarrier(++ph * NCTA);
    }

    // ---- final hidden state -> d_out tail [B, L, H] ----
    if (tid < 128) {
        int b = tid >> 2, c = tid & 3, gc = cta * NCOL + c;
        out[OUT_HID_OFF + (b * 2 + 0) * HID + gc] = g_h0[b * HID + gc];
        out[OUT_HID_OFF + (b * 2 + 1) * HID + gc] = g_h1[b * HID + gc];
    }
}

// ---------------------------------------------------------------------------
// deferred output projection: y[r, :] = h1all[r, :] @ Why^T + by
// grid = (131072/32 row-tiles, 4 col-groups of 64), 256 threads
// ---------------------------------------------------------------------------
__global__ void __launch_bounds__(256)
y_proj_kernel(const float* __restrict__ Why, const float* __restrict__ by,
              float* __restrict__ out) {
    extern __shared__ float sm[];
    float* sWy = sm;                 // [64][YW_STR]
    float* sIn = sm + 64 * YW_STR;   // [32][256]

    const int tid  = threadIdx.x;
    const int row0 = blockIdx.x * 32;
    const int cg   = blockIdx.y;

    // stage Why slice (64 rows x 256, padded stride)
    for (int u = tid; u < 64 * 64; u += 256) {
        int r = u >> 6, kk = u & 63;
        reinterpret_cast<float4*>(sWy)[r * (YW_STR / 4) + kk] =
            reinterpret_cast<const float4*>(Why + (size_t)(cg * 64 + r) * HID)[kk];
    }
    // stage 32 input rows
    for (int u = tid; u < 32 * 64; u += 256) {
        int r = u >> 6, kk = u & 63;
        reinterpret_cast<float4*>(sIn)[u] =
            reinterpret_cast<const float4*>(g_h1all + (size_t)(row0 + r) * HID)[kk];
    }
    __syncthreads();

    const int c2 = tid & 31;   // column within group; handles cols c2 and c2+32
    const int r4 = tid >> 5;   // row quad
    unsigned long long acc[4][2];
#pragma unroll
    for (int j = 0; j < 4; ++j) { acc[j][0] = 0ull; acc[j][1] = 0ull; }

    for (int i = 0; i < 64; ++i) {
        ulonglong2 inv[4];
#pragma unroll
        for (int j = 0; j < 4; ++j)
            inv[j] = *reinterpret_cast<const ulonglong2*>(sIn + (r4 * 4 + j) * HID + 4 * i);
#pragma unroll
        for (int cc = 0; cc < 2; ++cc) {
            ulonglong2 wv = *reinterpret_cast<const ulonglong2*>(
                sWy + (cc * 32 + c2) * YW_STR + 4 * i);
#pragma unroll
            for (int j = 0; j < 4; ++j) {
                fma2(acc[j][cc], wv.x, inv[j].x);
                fma2(acc[j][cc], wv.y, inv[j].y);
            }
        }
    }
#pragma unroll
    for (int j = 0; j < 4; ++j)
#pragma unroll
        for (int cc = 0; cc < 2; ++cc) {
            int gc = cg * 64 + cc * 32 + c2;
            out[(size_t)(row0 + r4 * 4 + j) * OUTD + gc] = red2(acc[j][cc]) + __ldg(by + gc);
        }
}

// ---------------------------------------------------------------------------
// launch
// ---------------------------------------------------------------------------
extern "C" void kernel_launch(void* const* d_in, const int* in_sizes, int n_in,
                              void* d_out, int out_size) {
    (void)in_sizes; (void)n_in; (void)out_size;
    const float* input  = (const float*)d_in[0];
    const float* hstate = (const float*)d_in[1];
    const float* Wxz    = (const float*)d_in[2];
    const float* Whz    = (const float*)d_in[3];
    const float* bz     = (const float*)d_in[4];
    const float* Wxr    = (const float*)d_in[5];
    const float* Whr    = (const float*)d_in[6];
    const float* br     = (const float*)d_in[7];
    const float* Wxg    = (const float*)d_in[8];
    const float* Whg    = (const float*)d_in[9];
    const float* bg     = (const float*)d_in[10];
    const float* Why    = (const float*)d_in[11];
    const float* by     = (const float*)d_in[12];
    float* out = (float*)d_out;

    cudaFuncSetAttribute(gru_persistent,
                         cudaFuncAttributeMaxDynamicSharedMemorySize, SMEM_BYTES);
    cudaFuncSetAttribute(y_proj_kernel,
                         cudaFuncAttributeMaxDynamicSharedMemorySize, YSMEM_BYTES);

    bar_init_kernel<<<1, 1>>>();
    gru_persistent<<<NCTA, NTHR, SMEM_BYTES>>>(input, hstate, Wxz, Whz, bz,
                                               Wxr, Whr, br, Wxg, Whg, bg, out);
    dim3 ygrid(BATCH * SEQ / 32, OUTD / 64);
    y_proj_kernel<<<ygrid, 256, YSMEM_BYTES>>>(Why, by, out);
}

// round 9
// speedup vs baseline: 1.9585x; 1.9585x over previous
#include <cuda_runtime.h>

// ---------------------------------------------------------------------------
// MultilayerGRU: B=32, S=4096, H=256, O=256, L=2
// Wavefront persistent kernel: 64 CTAs per layer, layer 1 lags one step.
// 2 grid barriers per step. Weights resident in SMEM. Deferred y-projection.
// ---------------------------------------------------------------------------

#define BATCH 32
#define HID   256
#define SEQ   4096
#define OUTD  256
#define NCTA  128        // 64 layer-0 + 64 layer-1
#define NCOL  4          // output columns owned per CTA
#define NTHR  256

#define OUT_HID_OFF (BATCH * SEQ * OUTD)

// ---- persistent-kernel SMEM layout (floats) ----
#define SW_OFF   0
#define SW_SZ    (6 * NCOL * HID)          // 6144: Wxz Wxr Wxg Whz Whr Whg (own 4 rows)
#define SX0_OFF  (SW_OFF + SW_SZ)          // v buffer 0 (x ping / L1: h0')
#define SX1_OFF  (SX0_OFF + BATCH * HID)   // v buffer 1 (x pong)
#define SH_OFF   (SX1_OFF + BATCH * HID)   // h_prev
#define SR_OFF   (SH_OFF + BATCH * HID)    // h*r
#define SP_OFF   (SR_OFF + BATCH * HID)    // partials [4 pairs][2 gates][32][4]
#define SB_OFF   (SP_OFF + 1024)           // biases z(4) r(4) g(4), pad 16
#define SM_FLOATS (SB_OFF + 16)
#define SMEM_BYTES (SM_FLOATS * 4)         // 160,448 bytes

// ---- y-projection kernel SMEM ----
#define YW_STR 260
#define YSMEM_FLOATS (64 * YW_STR + 32 * HID)
#define YSMEM_BYTES  (YSMEM_FLOATS * 4)

// ---- static device state ----
__device__ float    g_h0[BATCH * HID];
__device__ float    g_h1[BATCH * HID];
__device__ float    g_hr0[BATCH * HID];
__device__ float    g_hr1[BATCH * HID];
__device__ float    g_h1all[BATCH * SEQ * HID];   // 134 MB h1 history
__device__ unsigned g_bar;

__global__ void bar_init_kernel() { g_bar = 0u; }
__global__ void ncu_pad_kernel() {}

// ---------------------------------------------------------------------------
// helpers
// ---------------------------------------------------------------------------

__device__ __forceinline__ void fma2(unsigned long long& acc,
                                     unsigned long long a, unsigned long long b) {
    asm("fma.rn.f32x2 %0, %1, %2, %0;" : "+l"(acc) : "l"(a), "l"(b));
}

__device__ __forceinline__ float red2(unsigned long long a) {
    float lo = __uint_as_float((unsigned)(a & 0xffffffffull));
    float hi = __uint_as_float((unsigned)(a >> 32));
    return lo + hi;
}

__device__ __forceinline__ float redk(unsigned long long a) {
    float f = red2(a);
    f += __shfl_xor_sync(0xffffffffu, f, 1);
    f += __shfl_xor_sync(0xffffffffu, f, 2);
    f += __shfl_xor_sync(0xffffffffu, f, 4);
    return f;
}

__device__ __forceinline__ float sigm(float x) { return 1.0f / (1.0f + expf(-x)); }

__device__ __forceinline__ void gbarrier(unsigned target) {
    __threadfence();
    __syncthreads();
    if (threadIdx.x == 0) {
        asm volatile("red.release.gpu.global.add.u32 [%0], %1;"
                     :: "l"(&g_bar), "r"(1u) : "memory");
        unsigned v = 0;
        do {
            asm volatile("ld.acquire.gpu.global.u32 %0, [%1];"
                         : "=r"(v) : "l"(&g_bar) : "memory");
        } while (v < target);
    }
    __syncthreads();
}

// cp.async 16B
__device__ __forceinline__ void cp16(float* dst_smem, const float* src) {
    unsigned d = (unsigned)__cvta_generic_to_shared(dst_smem);
    asm volatile("cp.async.cg.shared.global [%0], [%1], 16;" :: "r"(d), "l"(src));
}
#define CP_COMMIT() asm volatile("cp.async.commit_group;")
#define CP_WAIT0()  asm volatile("cp.async.wait_group 0;")
#define CP_WAIT1()  asm volatile("cp.async.wait_group 1;")

// stage [32][256] contiguous vector -> smem (2048 float4, 8 per thread)
__device__ __forceinline__ void stage_async(float* dst, const float* src, int tid) {
#pragma unroll
    for (int j = 0; j < 8; ++j) {
        int u = tid + NTHR * j;
        cp16(dst + u * 4, src + u * 4);
    }
}

// stage x(t): rows strided by SEQ*HID
__device__ __forceinline__ void stage_x_async(float* dst, const float* input,
                                              int t, int tid) {
#pragma unroll
    for (int j = 0; j < 8; ++j) {
        int u = tid + NTHR * j;
        int b = u >> 6, kk = u & 63;
        cp16(dst + u * 4, input + ((size_t)b * SEQ + t) * HID + kk * 4);
    }
}

// ---------------------------------------------------------------------------
// tick A GEMM: two matrices (z & r share the v load), K-half kh.
// pair = wid>>1 in 0..3, half = wid&1 splits batches, q = lane>>3, ks = lane&7
// ---------------------------------------------------------------------------
__device__ __forceinline__ void gemmA(const float* __restrict__ v,
                                      const float* __restrict__ w0,
                                      const float* __restrict__ w1,
                                      int kh, float* __restrict__ sPart,
                                      int pair, int half, int q, int ks) {
    unsigned long long acc[4][8];
#pragma unroll
    for (int jj = 0; jj < 4; ++jj)
#pragma unroll
        for (int m = 0; m < 8; ++m) acc[jj][m] = 0ull;

    const int b0 = half * 16 + q * 4;
#pragma unroll
    for (int i = 0; i < 4; ++i) {
        const int kk = kh * 128 + i * 32 + ks * 4;
        ulonglong2 vv[4];
#pragma unroll
        for (int jj = 0; jj < 4; ++jj)
            vv[jj] = *reinterpret_cast<const ulonglong2*>(v + (b0 + jj) * HID + kk);
        ulonglong2 wv[8];
#pragma unroll
        for (int c = 0; c < 4; ++c) {
            wv[c]     = *reinterpret_cast<const ulonglong2*>(w0 + c * HID + kk);
            wv[4 + c] = *reinterpret_cast<const ulonglong2*>(w1 + c * HID + kk);
        }
#pragma unroll
        for (int jj = 0; jj < 4; ++jj)
#pragma unroll
            for (int m = 0; m < 8; ++m) {
                fma2(acc[jj][m], wv[m].x, vv[jj].x);
                fma2(acc[jj][m], wv[m].y, vv[jj].y);
            }
    }
#pragma unroll
    for (int jj = 0; jj < 4; ++jj)
#pragma unroll
        for (int m = 0; m < 8; ++m) {
            float f = redk(acc[jj][m]);
            if (ks == 0)
                sPart[((pair * 2 + (m >> 2)) * 32 + b0 + jj) * 4 + (m & 3)] = f;
        }
}

// tick B GEMM: single matrix
__device__ __forceinline__ void gemmB(const float* __restrict__ v,
                                      const float* __restrict__ w0,
                                      int kh, float* __restrict__ sPart,
                                      int pair, int half, int q, int ks) {
    unsigned long long acc[4][4];
#pragma unroll
    for (int jj = 0; jj < 4; ++jj)
#pragma unroll
        for (int c = 0; c < 4; ++c) acc[jj][c] = 0ull;

    const int b0 = half * 16 + q * 4;
#pragma unroll
    for (int i = 0; i < 4; ++i) {
        const int kk = kh * 128 + i * 32 + ks * 4;
        ulonglong2 vv[4];
#pragma unroll
        for (int jj = 0; jj < 4; ++jj)
            vv[jj] = *reinterpret_cast<const ulonglong2*>(v + (b0 + jj) * HID + kk);
        ulonglong2 wv[4];
#pragma unroll
        for (int c = 0; c < 4; ++c)
            wv[c] = *reinterpret_cast<const ulonglong2*>(w0 + c * HID + kk);
#pragma unroll
        for (int jj = 0; jj < 4; ++jj)
#pragma unroll
            for (int c = 0; c < 4; ++c) {
                fma2(acc[jj][c], wv[c].x, vv[jj].x);
                fma2(acc[jj][c], wv[c].y, vv[jj].y);
            }
    }
#pragma unroll
    for (int jj = 0; jj < 4; ++jj)
#pragma unroll
        for (int c = 0; c < 4; ++c) {
            float f = redk(acc[jj][c]);
            if (ks == 0)
                sPart[((pair * 2) * 32 + b0 + jj) * 4 + c] = f;
        }
}

// ---------------------------------------------------------------------------
// persistent wavefront GRU: 128 CTAs x 256 threads
// ---------------------------------------------------------------------------
__global__ void __launch_bounds__(NTHR, 1)
gru_persistent(const float* __restrict__ input, const float* __restrict__ hstate,
               const float* __restrict__ Wxz, const float* __restrict__ Whz,
               const float* __restrict__ bz,
               const float* __restrict__ Wxr, const float* __restrict__ Whr,
               const float* __restrict__ br,
               const float* __restrict__ Wxg, const float* __restrict__ Whg,
               const float* __restrict__ bg,
               float* __restrict__ out) {
    extern __shared__ float sm[];
    float* sW    = sm + SW_OFF;
    float* sX0   = sm + SX0_OFF;
    float* sX1   = sm + SX1_OFF;
    float* sH    = sm + SH_OFF;
    float* sR    = sm + SR_OFF;
    float* sPart = sm + SP_OFF;
    float* sBias = sm + SB_OFF;

    const int tid   = threadIdx.x;
    const int cta   = blockIdx.x;
    const int layer = cta >> 6;          // 0 or 1
    const int cid   = cta & 63;          // CTA within layer
    const int wid   = tid >> 5;
    const int lane  = tid & 31;
    const int pair  = wid >> 1;
    const int half  = wid & 1;
    const int q     = lane >> 3;
    const int ks    = lane & 7;
    const int kh    = pair & 1;

    // ---- resident weights: rows cid*4 .. cid*4+3 of the 6 own-layer matrices ----
    {
        const size_t loff = (size_t)layer * HID * HID;
        const float* wsrc[6] = { Wxz + loff, Wxr + loff, Wxg + loff,
                                 Whz + loff, Whr + loff, Whg + loff };
#pragma unroll
        for (int m = 0; m < 6; ++m) {
            const float4* s = reinterpret_cast<const float4*>(wsrc[m] + cid * NCOL * HID);
            float4* d = reinterpret_cast<float4*>(sW + m * NCOL * HID);
            for (int u = tid; u < NCOL * HID / 4; u += NTHR) d[u] = s[u];
        }
    }
    // biases: z(0-3) r(4-7) g(8-11)
    if (tid < 12) {
        int g = tid >> 2, c = tid & 3;
        const float* bsrc = (g == 0) ? bz : ((g == 1) ? br : bg);
        sBias[tid] = bsrc[layer * HID + cid * NCOL + c];
    }
    // init hidden state (own columns)
    if (tid < 128) {
        int b = tid >> 2, c = tid & 3, gc = cid * NCOL + c;
        if (layer == 0) g_h0[b * HID + gc] = hstate[(b * 2 + 0) * HID + gc];
        else            g_h1[b * HID + gc] = hstate[(b * 2 + 1) * HID + gc];
    }
    // L0: prefetch x(0)
    if (layer == 0) {
        stage_x_async(sX0, input, 0, tid);
        CP_COMMIT();
    }

    unsigned ph = 0;
    gbarrier(++ph * NCTA);

    float zreg = 0.f, hreg = 0.f;

    for (int sIdx = 0; sIdx <= SEQ; ++sIdx) {
        const bool active = (layer == 0) ? (sIdx < SEQ) : (sIdx >= 1);
        const int  t      = (layer == 0) ? sIdx : sIdx - 1;
        float* sV = (layer == 0) ? ((sIdx & 1) ? sX1 : sX0) : sX0;

        // ---- tick A: stage h (and v for L1) ----
        if (active) {
            stage_async(sH, (layer == 0) ? g_h0 : g_h1, tid);
            if (layer == 1) stage_async(sV, g_h0, tid);
            CP_COMMIT();
        }
        CP_WAIT0();
        __syncthreads();

        if (active) {
            const float* v = (pair < 2) ? sV : sH;
            const float* w0 = sW + ((pair < 2) ? 0 : 3) * (NCOL * HID);
            const float* w1 = sW + ((pair < 2) ? 1 : 4) * (NCOL * HID);
            gemmA(v, w0, w1, kh, sPart, pair, half, q, ks);
        }
        __syncthreads();

        if (active && tid < 128) {
            int b = tid >> 2, c = tid & 3, gc = cid * NCOL + c;
            float zs = 0.f, rs = 0.f;
#pragma unroll
            for (int p = 0; p < 4; ++p) {
                zs += sPart[((p * 2 + 0) * 32 + b) * 4 + c];
                rs += sPart[((p * 2 + 1) * 32 + b) * 4 + c];
            }
            float z = sigm(zs + sBias[c]);
            float r = sigm(rs + sBias[4 + c]);
            hreg = sH[b * HID + gc];
            zreg = z;
            float* hrdst = (layer == 0) ? g_hr0 : g_hr1;
            hrdst[b * HID + gc] = hreg * r;
        }
        gbarrier(++ph * NCTA);

        // ---- tick B: stage h*r ; L0 prefetches x(t+1) ----
        if (active) {
            stage_async(sR, (layer == 0) ? g_hr0 : g_hr1, tid);
            CP_COMMIT();
        }
        const bool pf = (layer == 0) && (sIdx + 1 < SEQ);
        if (pf) {
            float* dst = ((sIdx + 1) & 1) ? sX1 : sX0;
            stage_x_async(dst, input, sIdx + 1, tid);
            CP_COMMIT();
            CP_WAIT1();                 // wait sR only; prefetch stays in flight
        } else {
            CP_WAIT0();
        }
        __syncthreads();

        if (active) {
            const float* v = (pair < 2) ? sV : sR;
            const float* w0 = sW + ((pair < 2) ? 2 : 5) * (NCOL * HID);
            gemmB(v, w0, kh, sPart, pair, half, q, ks);
        }
        __syncthreads();

        if (active && tid < 128) {
            int b = tid >> 2, c = tid & 3, gc = cid * NCOL + c;
            float gs = 0.f;
#pragma unroll
            for (int p = 0; p < 4; ++p)
                gs += sPart[((p * 2) * 32 + b) * 4 + c];
            float g  = tanhf(gs + sBias[8 + c]);
            float hn = zreg * hreg + (1.0f - zreg) * g;
            if (layer == 0) {
                g_h0[b * HID + gc] = hn;
            } else {
                g_h1[b * HID + gc] = hn;
                g_h1all[((size_t)b * SEQ + t) * HID + gc] = hn;
            }
        }
        gbarrier(++ph * NCTA);
    }

    // ---- final hidden state -> d_out tail [B, L, H] ----
    if (tid < 128) {
        int b = tid >> 2, c = tid & 3, gc = cid * NCOL + c;
        if (layer == 0)
            out[OUT_HID_OFF + (b * 2 + 0) * HID + gc] = g_h0[b * HID + gc];
        else
            out[OUT_HID_OFF + (b * 2 + 1) * HID + gc] = g_h1[b * HID + gc];
    }
}

// ---------------------------------------------------------------------------
// deferred output projection: y[r,:] = h1all[r,:] @ Why^T + by
// ---------------------------------------------------------------------------
__global__ void __launch_bounds__(256)
y_proj_kernel(const float* __restrict__ Why, const float* __restrict__ by,
              float* __restrict__ out) {
    extern __shared__ float sm[];
    float* sWy = sm;                 // [64][YW_STR]
    float* sIn = sm + 64 * YW_STR;   // [32][256]

    const int tid  = threadIdx.x;
    const int row0 = blockIdx.x * 32;
    const int cg   = blockIdx.y;

    for (int u = tid; u < 64 * 64; u += 256) {
        int r = u >> 6, kk = u & 63;
        reinterpret_cast<float4*>(sWy)[r * (YW_STR / 4) + kk] =
            reinterpret_cast<const float4*>(Why + (size_t)(cg * 64 + r) * HID)[kk];
    }
    for (int u = tid; u < 32 * 64; u += 256) {
        int r = u >> 6, kk = u & 63;
        reinterpret_cast<float4*>(sIn)[u] =
            reinterpret_cast<const float4*>(g_h1all + (size_t)(row0 + r) * HID)[kk];
    }
    __syncthreads();

    const int c2 = tid & 31;
    const int r4 = tid >> 5;
    unsigned long long acc[4][2];
#pragma unroll
    for (int j = 0; j < 4; ++j) { acc[j][0] = 0ull; acc[j][1] = 0ull; }

    for (int i = 0; i < 64; ++i) {
        ulonglong2 inv[4];
#pragma unroll
        for (int j = 0; j < 4; ++j)
            inv[j] = *reinterpret_cast<const ulonglong2*>(sIn + (r4 * 4 + j) * HID + 4 * i);
#pragma unroll
        for (int cc = 0; cc < 2; ++cc) {
            ulonglong2 wv = *reinterpret_cast<const ulonglong2*>(
                sWy + (cc * 32 + c2) * YW_STR + 4 * i);
#pragma unroll
            for (int j = 0; j < 4; ++j) {
                fma2(acc[j][cc], wv.x, inv[j].x);
                fma2(acc[j][cc], wv.y, inv[j].y);
            }
        }
    }
#pragma unroll
    for (int j = 0; j < 4; ++j)
#pragma unroll
        for (int cc = 0; cc < 2; ++cc) {
            int gc = cg * 64 + cc * 32 + c2;
            out[(size_t)(row0 + r4 * 4 + j) * OUTD + gc] = red2(acc[j][cc]) + __ldg(by + gc);
        }
}

// ---------------------------------------------------------------------------
// launch: per-call pattern [bar_init, gru, y_proj, pad] so ncu -s 5 -c 1
// (5 mod 4 == 1) lands on gru_persistent.
// ---------------------------------------------------------------------------
extern "C" void kernel_launch(void* const* d_in, const int* in_sizes, int n_in,
                              void* d_out, int out_size) {
    (void)in_sizes; (void)n_in; (void)out_size;
    const float* input  = (const float*)d_in[0];
    const float* hstate = (const float*)d_in[1];
    const float* Wxz    = (const float*)d_in[2];
    const float* Whz    = (const float*)d_in[3];
    const float* bz     = (const float*)d_in[4];
    const float* Wxr    = (const float*)d_in[5];
    const float* Whr    = (const float*)d_in[6];
    const float* br     = (const float*)d_in[7];
    const float* Wxg    = (const float*)d_in[8];
    const float* Whg    = (const float*)d_in[9];
    const float* bg     = (const float*)d_in[10];
    const float* Why    = (const float*)d_in[11];
    const float* by     = (const float*)d_in[12];
    float* out = (float*)d_out;

    cudaFuncSetAttribute(gru_persistent,
                         cudaFuncAttributeMaxDynamicSharedMemorySize, SMEM_BYTES);
    cudaFuncSetAttribute(y_proj_kernel,
                         cudaFuncAttributeMaxDynamicSharedMemorySize, YSMEM_BYTES);

    bar_init_kernel<<<1, 1>>>();
    gru_persistent<<<NCTA, NTHR, SMEM_BYTES>>>(input, hstate, Wxz, Whz, bz,
                                               Wxr, Whr, br, Wxg, Whg, bg, out);
    dim3 ygrid(BATCH * SEQ / 32, OUTD / 64);
    y_proj_kernel<<<ygrid, 256, YSMEM_BYTES>>>(Why, by, out);
    ncu_pad_kernel<<<1, 1>>>();
}